// round 16
// baseline (speedup 1.0000x reference)
#include <cuda_runtime.h>
#include <cuda_bf16.h>
#include <cstdint>
#include <math.h>

// Problem constants (fixed shapes from setup_inputs)
#define M_ROWS 16384   // B*T
#define N_POS  4096
#define D_DIM  512

// ---------------------------------------------------------------------------
// Scratch (__device__ globals; device-side access ONLY — host-passing a
// __device__ symbol as a kernel arg passes the inert host shadow (r5-r9 bug)).
//
// Interleaved hi/lo layout: arrays of 32-bit words; for pair index p
// (elements 2p, 2p+1): word 2p = [hi(2p), hi(2p+1)], word 2p+1 = [lo pair].
// A row of E elements occupies E words. One LDS.64 yields (hi, lo) words.
// ---------------------------------------------------------------------------
__device__ __align__(1024) uint32_t g_Xp[(size_t)M_ROWS * D_DIM];   // 32 MiB
__device__ __align__(1024) uint32_t g_Pp[(size_t)N_POS * D_DIM];    //  8 MiB
__device__ __align__(1024) uint32_t g_Vtp[(size_t)D_DIM * N_POS];   //  8 MiB (V^T)
__device__ __align__(1024) uint32_t g_Wp[(size_t)M_ROWS * N_POS];   // 256 MiB
__device__ __align__(1024) float g_xn[M_ROWS];
__device__ __align__(1024) float g_pn[N_POS];
__device__ __align__(1024) float g_invt[N_POS];
__device__ __align__(1024) float g_part[(size_t)M_ROWS * 16];
__device__ __align__(1024) float g_rowsum[M_ROWS];

// ---------------------------------------------------------------------------
// Base-target helpers (no 'a'-gated instructions: harness targets sm_103)
// ---------------------------------------------------------------------------
__device__ __forceinline__ uint32_t smem_u32(const void* p) {
    uint32_t a;
    asm("{ .reg .u64 t; cvta.to.shared.u64 t, %1; cvt.u32.u64 %0, t; }" : "=r"(a) : "l"(p));
    return a;
}
__device__ __forceinline__ void cp16(uint32_t dst, const void* src) {
    asm volatile("cp.async.cg.shared.global [%0], [%1], 16;" :: "r"(dst), "l"(src));
}
#define CP_COMMIT()  asm volatile("cp.async.commit_group;" ::: "memory")
#define CP_WAIT_0()  asm volatile("cp.async.wait_group 0;" ::: "memory")
#define CP_WAIT_1()  asm volatile("cp.async.wait_group 1;" ::: "memory")

__device__ __forceinline__ void lds64(uint32_t& x, uint32_t& y, uint32_t a) {
    asm volatile("ld.shared.v2.u32 {%0,%1}, [%2];" : "=r"(x), "=r"(y) : "r"(a));
}
__device__ __forceinline__ void mma16816(float* d, const uint32_t* a, uint32_t b0, uint32_t b1) {
    asm volatile("mma.sync.aligned.m16n8k16.row.col.f32.bf16.bf16.f32 "
        "{%0,%1,%2,%3}, {%4,%5,%6,%7}, {%8,%9}, {%0,%1,%2,%3};"
        : "+f"(d[0]), "+f"(d[1]), "+f"(d[2]), "+f"(d[3])
        : "r"(a[0]), "r"(a[1]), "r"(a[2]), "r"(a[3]), "r"(b0), "r"(b1));
}
__device__ __forceinline__ uint32_t pack_hi2(float a, float b) {
    __nv_bfloat162 t; t.x = __float2bfloat16(a); t.y = __float2bfloat16(b);
    return *(uint32_t*)&t;
}

// ---------------------------------------------------------------------------
// SMEM layout. CTA tile M=128, N=256, K-chunk=64 elements. Warp tile 64x64.
// Row = 64 elements = 64 words (hi/lo interleaved) = 256B, padded to 272B:
// word stride 68 ≡ 4 (mod 32) -> LDS.64 pattern 4*lg+2*lt hits every even
// bank exactly 2x = 2-phase minimum -> conflict-free-effective.
// ---------------------------------------------------------------------------
#define ROW_BYTES 272
#define A_TILE_BYTES (128 * ROW_BYTES)    // 34816
#define B_TILE_BYTES (256 * ROW_BYTES)    // 69632
#define OFF_PN   0                        // 256 floats
#define OFF_IT   1024                     // 256 floats
#define OFF_RED  2048                     // 128*4 floats
#define OFF_BUF  4096
#define A_BUF(b) (OFF_BUF + (b) * A_TILE_BYTES)
#define B_BUF(b) (OFF_BUF + 2 * A_TILE_BYTES + (b) * B_TILE_BYTES)
#define SMEM_TOTAL (OFF_BUF + 2 * A_TILE_BYTES + 2 * B_TILE_BYTES)   // 212992

// Load an NROWS x 64-element tile (64 words/row) into padded smem (256 thr)
template <int NROWS>
__device__ __forceinline__ void load_tile(uint32_t base, uint32_t dst_off,
                                          const uint32_t* __restrict__ src,
                                          int row0, int ld, int k0, int tid) {
    #pragma unroll
    for (int i = 0; i < NROWS / 16; i++) {   // NROWS*16 chunks / 256 threads
        int idx = tid + i * 256;
        int row = idx >> 4, cc = idx & 15;
        const void* g = src + (size_t)(row0 + row) * ld + k0 + cc * 4;
        cp16(base + dst_off + (uint32_t)(row * ROW_BYTES + cc * 16), g);
    }
}

__device__ __forceinline__ void load_stage(uint32_t base, int b,
        const uint32_t* A, int ldA, int arow0,
        const uint32_t* B, int ldB, int brow0, int k0, int tid) {
    load_tile<128>(base, A_BUF(b), A, arow0, ldA, k0, tid);
    load_tile<256>(base, B_BUF(b), B, brow0, ldB, k0, tid);
}

// Compute one K=64 chunk. Warp tile 64x64: mf=4, nf=8; 3 hi/lo products.
// Fragment words per PTX mma.m16n8k16 tables (g=lane>>2, t=lane&3):
// pair p = kk*8 + t (b0/a0,a1) and p+4 (b1/a2,a3); word byte = 8p.
__device__ __forceinline__ void compute_chunk(uint32_t base, int b, int wm, int wn,
                                              int lane, float acc[4][8][4]) {
    uint32_t Ab = base + A_BUF(b);
    uint32_t Bb = base + B_BUF(b);
    const int lg = lane >> 2, lt = lane & 3;
    #pragma unroll
    for (int kk = 0; kk < 4; kk++) {
        const uint32_t kb = (uint32_t)(kk * 64 + lt * 8);
        uint32_t bh0[8], bh1[8], bl0[8], bl1[8];
        #pragma unroll
        for (int nf = 0; nf < 8; nf++) {
            uint32_t ro = Bb + (uint32_t)((wn * 64 + nf * 8 + lg) * ROW_BYTES) + kb;
            lds64(bh0[nf], bl0[nf], ro);
            lds64(bh1[nf], bl1[nf], ro + 32);
        }
        #pragma unroll
        for (int mf = 0; mf < 4; mf++) {
            uint32_t r0 = Ab + (uint32_t)((wm * 64 + mf * 16 + lg) * ROW_BYTES) + kb;
            uint32_t r1 = r0 + 8 * ROW_BYTES;
            uint32_t ah[4], al[4];
            lds64(ah[0], al[0], r0);
            lds64(ah[2], al[2], r0 + 32);
            lds64(ah[1], al[1], r1);
            lds64(ah[3], al[3], r1 + 32);
            #pragma unroll
            for (int nf = 0; nf < 8; nf++) {
                mma16816(acc[mf][nf], ah, bh0[nf], bh1[nf]);  // hi*hi
                mma16816(acc[mf][nf], ah, bl0[nf], bl1[nf]);  // hi*lo
                mma16816(acc[mf][nf], al, bh0[nf], bh1[nf]);  // lo*hi
            }
        }
    }
}

// Double-buffered cp.async mainloop — PROVEN r13/14 ordering:
//   load-next -> commit -> wait(own groups) -> BAR -> compute -> BAR.
// The first BAR makes every warp's chunk-c data visible (each warp waited on
// its own groups before the BAR); the second BAR keeps any warp from
// overwriting buffer b while others still compute on it.
__device__ __forceinline__ void gemm_main(uint32_t base, int tid,
        int wm, int wn, int lane,
        const uint32_t* A, int ldA, int arow0,
        const uint32_t* B, int ldB, int brow0,
        int C, float acc[4][8][4]) {
    load_stage(base, 0, A, ldA, arow0, B, ldB, brow0, 0, tid);
    CP_COMMIT();
    for (int c = 0; c < C; c++) {
        int b = c & 1;
        if (c + 1 < C) {
            load_stage(base, b ^ 1, A, ldA, arow0, B, ldB, brow0, (c + 1) * 64, tid);
            CP_COMMIT();
            CP_WAIT_1();
        } else {
            CP_WAIT_0();
        }
        __syncthreads();
        compute_chunk(base, b, wm, wn, lane, acc);
        __syncthreads();
    }
}

// ---------------------------------------------------------------------------
// GEMM1: S = X @ P^T (TN), epilogue w = exp(-dist*invt) -> W (hi/lo) + partials
// ---------------------------------------------------------------------------
__global__ __launch_bounds__(256) void gemm1_mma() {
    extern __shared__ char smem[];
    uint32_t base = smem_u32(smem);
    int tid = threadIdx.x, wid = tid >> 5, lane = tid & 31;
    int wm = wid >> 2, wn = wid & 3;
    int bm = blockIdx.y * 128, bn = blockIdx.x * 256;

    float* sm_pn = (float*)(smem + OFF_PN);
    float* sm_it = (float*)(smem + OFF_IT);
    sm_pn[tid] = g_pn[bn + tid];
    sm_it[tid] = g_invt[bn + tid];

    float acc[4][8][4];
    #pragma unroll
    for (int i = 0; i < 4; i++)
        #pragma unroll
        for (int j = 0; j < 8; j++)
            #pragma unroll
            for (int k = 0; k < 4; k++) acc[i][j][k] = 0.0f;

    gemm_main(base, tid, wm, wn, lane, g_Xp, D_DIM, bm,
              g_Pp, D_DIM, bn, D_DIM / 64, acc);

    // Epilogue
    float* redrows = (float*)(smem + OFF_RED);
    float rps[4][2];
    #pragma unroll
    for (int mf = 0; mf < 4; mf++) { rps[mf][0] = 0.0f; rps[mf][1] = 0.0f; }

    #pragma unroll
    for (int mf = 0; mf < 4; mf++) {
        int r0l = wm * 64 + mf * 16 + (lane >> 2);
        float xn0 = g_xn[bm + r0l], xn1 = g_xn[bm + r0l + 8];
        #pragma unroll
        for (int nf = 0; nf < 8; nf++) {
            int c0 = wn * 64 + nf * 8 + (lane & 3) * 2;
            float pn0 = sm_pn[c0], pn1 = sm_pn[c0 + 1];
            float it0 = sm_it[c0], it1 = sm_it[c0 + 1];
            #pragma unroll
            for (int half = 0; half < 2; half++) {
                float xn = half ? xn1 : xn0;
                float s0 = acc[mf][nf][half * 2 + 0];
                float s1 = acc[mf][nf][half * 2 + 1];
                float d20 = fmaxf(xn + pn0 - 2.0f * s0, 0.0f);
                float d21 = fmaxf(xn + pn1 - 2.0f * s1, 0.0f);
                float w0 = __expf(-sqrtf(d20) * it0);
                float w1 = __expf(-sqrtf(d21) * it1);
                rps[mf][half] += w0 + w1;
                uint32_t hp = pack_hi2(w0, w1);
                __nv_bfloat162 hb = *(__nv_bfloat162*)&hp;
                uint32_t lp = pack_hi2(w0 - __bfloat162float(hb.x),
                                       w1 - __bfloat162float(hb.y));
                // words (c0, c0+1) of row: [hi pair, lo pair]
                size_t gw = (size_t)(bm + r0l + half * 8) * N_POS + bn + c0;
                *(uint2*)(g_Wp + gw) = make_uint2(hp, lp);
            }
        }
    }
    // Deterministic rowsum partials (4 lanes/row -> 4 warp-cols -> 1 value)
    #pragma unroll
    for (int mf = 0; mf < 4; mf++)
        #pragma unroll
        for (int half = 0; half < 2; half++) {
            float v = rps[mf][half];
            v += __shfl_xor_sync(0xffffffffu, v, 1);
            v += __shfl_xor_sync(0xffffffffu, v, 2);
            if ((lane & 3) == 0)
                redrows[(wm * 64 + mf * 16 + (lane >> 2) + half * 8) * 4 + wn] = v;
        }
    __syncthreads();
    if (tid < 128) {
        float s = redrows[tid * 4 + 0] + redrows[tid * 4 + 1]
                + redrows[tid * 4 + 2] + redrows[tid * 4 + 3];
        g_part[(size_t)(bm + tid) * 16 + blockIdx.x] = s;
    }
}

// ---------------------------------------------------------------------------
// GEMM2: out = (W @ V) / (rowsum + 1e-8)   (TN with B = V^T)
// ---------------------------------------------------------------------------
__global__ __launch_bounds__(256) void gemm2_mma(float* __restrict__ out) {
    extern __shared__ char smem[];
    uint32_t base = smem_u32(smem);
    int tid = threadIdx.x, wid = tid >> 5, lane = tid & 31;
    int wm = wid >> 2, wn = wid & 3;
    int bm = blockIdx.y * 128, dn = blockIdx.x * 256;

    float acc[4][8][4];
    #pragma unroll
    for (int i = 0; i < 4; i++)
        #pragma unroll
        for (int j = 0; j < 8; j++)
            #pragma unroll
            for (int k = 0; k < 4; k++) acc[i][j][k] = 0.0f;

    gemm_main(base, tid, wm, wn, lane, g_Wp, N_POS, bm,
              g_Vtp, N_POS, dn, N_POS / 64, acc);

    #pragma unroll
    for (int mf = 0; mf < 4; mf++) {
        int r0g = bm + wm * 64 + mf * 16 + (lane >> 2);
        float inv0 = 1.0f / (g_rowsum[r0g] + 1e-8f);
        float inv1 = 1.0f / (g_rowsum[r0g + 8] + 1e-8f);
        #pragma unroll
        for (int nf = 0; nf < 8; nf++) {
            int c0 = dn + wn * 64 + nf * 8 + (lane & 3) * 2;
            float2 v0 = make_float2(acc[mf][nf][0] * inv0, acc[mf][nf][1] * inv0);
            float2 v1 = make_float2(acc[mf][nf][2] * inv1, acc[mf][nf][3] * inv1);
            *(float2*)(out + (size_t)r0g * D_DIM + c0) = v0;
            *(float2*)(out + (size_t)(r0g + 8) * D_DIM + c0) = v1;
        }
    }
}

// ---------------------------------------------------------------------------
// Prep kernels (destinations are __device__ symbols, device-side access only)
// ---------------------------------------------------------------------------
__global__ void convert_x(const float* __restrict__ src) {
    int i = blockIdx.x * blockDim.x + threadIdx.x;   // elements 4i..4i+3
    if (i >= M_ROWS * D_DIM / 4) return;
    float4 v = ((const float4*)src)[i];
    uint32_t h0 = pack_hi2(v.x, v.y);
    uint32_t h1 = pack_hi2(v.z, v.w);
    __nv_bfloat162 b0 = *(__nv_bfloat162*)&h0;
    __nv_bfloat162 b1 = *(__nv_bfloat162*)&h1;
    uint32_t l0 = pack_hi2(v.x - __bfloat162float(b0.x), v.y - __bfloat162float(b0.y));
    uint32_t l1 = pack_hi2(v.z - __bfloat162float(b1.x), v.w - __bfloat162float(b1.y));
    ((uint4*)g_Xp)[i] = make_uint4(h0, l0, h1, l1);
}

__global__ void convert_p(const float* __restrict__ src) {
    int i = blockIdx.x * blockDim.x + threadIdx.x;
    if (i >= N_POS * D_DIM / 4) return;
    float4 v = ((const float4*)src)[i];
    uint32_t h0 = pack_hi2(v.x, v.y);
    uint32_t h1 = pack_hi2(v.z, v.w);
    __nv_bfloat162 b0 = *(__nv_bfloat162*)&h0;
    __nv_bfloat162 b1 = *(__nv_bfloat162*)&h1;
    uint32_t l0 = pack_hi2(v.x - __bfloat162float(b0.x), v.y - __bfloat162float(b0.y));
    uint32_t l1 = pack_hi2(v.z - __bfloat162float(b1.x), v.w - __bfloat162float(b1.y));
    ((uint4*)g_Pp)[i] = make_uint4(h0, l0, h1, l1);
}

__global__ void transpose_v(const float* __restrict__ V) {  // V[4096,512] -> Vt[512,4096]
    __shared__ float t[32][33];
    int d0 = blockIdx.x * 32, n0 = blockIdx.y * 32;
    int tx = threadIdx.x, ty = threadIdx.y;
    #pragma unroll
    for (int i = 0; i < 4; i++)
        t[ty + i * 8][tx] = V[(size_t)(n0 + ty + i * 8) * D_DIM + d0 + tx];
    __syncthreads();
    __nv_bfloat16* vt = (__nv_bfloat16*)g_Vtp;
    #pragma unroll
    for (int i = 0; i < 4; i++) {
        int d = d0 + ty + i * 8;
        int n = n0 + tx;
        float v = t[tx][ty + i * 8];
        __nv_bfloat16 h = __float2bfloat16(v);
        // bf16 idx: row d (4096 words = 8192 bf16), hi word 2*(n/2), half n&1
        size_t idx = (size_t)d * 8192 + (size_t)(n >> 1) * 4 + (n & 1);
        vt[idx] = h;
        vt[idx + 2] = __float2bfloat16(v - __bfloat162float(h));
    }
}

__device__ __forceinline__ float blockReduceSum(float v) {
    __shared__ float sh[32];
    int lane = threadIdx.x & 31, wid = threadIdx.x >> 5;
    #pragma unroll
    for (int o = 16; o > 0; o >>= 1) v += __shfl_down_sync(0xffffffffu, v, o);
    if (lane == 0) sh[wid] = v;
    __syncthreads();
    int nw = (blockDim.x + 31) >> 5;
    v = (threadIdx.x < nw) ? sh[threadIdx.x] : 0.0f;
    if (wid == 0)
        #pragma unroll
        for (int o = 16; o > 0; o >>= 1) v += __shfl_down_sync(0xffffffffu, v, o);
    return v;
}

__device__ __forceinline__ bool read_bool_elem(const void* p, int n) {
    unsigned int w0 = *(const unsigned int*)p;
    if (w0 == 0x3F800000u) return ((const float*)p)[n] != 0.0f;
    else if ((w0 & 0xFFu) != 0u && w0 != 1u) return ((const unsigned char*)p)[n] != 0;
    else return ((const int*)p)[n] != 0;
}

__global__ void row_norm_x_kernel(const float* __restrict__ X) {
    int row = blockIdx.x;
    const float* xr = X + (size_t)row * D_DIM;
    float s = 0.0f;
    for (int i = threadIdx.x; i < D_DIM; i += blockDim.x) { float v = xr[i]; s += v * v; }
    float tot = blockReduceSum(s);
    if (threadIdx.x == 0) g_xn[row] = tot;
}

__global__ void pos_stats_kernel(const float* __restrict__ P, const float* __restrict__ temp,
                                 const float* __restrict__ fscale, const void* __restrict__ frozen) {
    int n = blockIdx.x;
    const float* pr = P + (size_t)n * D_DIM;
    float s = 0.0f;
    for (int i = threadIdx.x; i < D_DIM; i += blockDim.x) { float v = pr[i]; s += v * v; }
    float tot = blockReduceSum(s);
    if (threadIdx.x == 0) {
        g_pn[n] = tot;
        float es = read_bool_elem(frozen, n) ? fscale[n] : 0.05f;
        g_invt[n] = 1.0f / ((fabsf(temp[n]) + 0.1f) * es);
    }
}

__global__ void reduce_parts() {
    int row = blockIdx.x * blockDim.x + threadIdx.x;
    if (row >= M_ROWS) return;
    float s = 0.0f;
    #pragma unroll
    for (int i = 0; i < 16; i++) s += g_part[(size_t)row * 16 + i];
    g_rowsum[row] = s;
}

// ---------------------------------------------------------------------------
// Launch
// ---------------------------------------------------------------------------
extern "C" void kernel_launch(void* const* d_in, const int* in_sizes, int n_in,
                              void* d_out, int out_size) {
    const float* x      = (const float*)d_in[0];
    const float* pos    = (const float*)d_in[1];
    const float* values = (const float*)d_in[2];
    const float* temp   = (const float*)d_in[3];
    const float* fscale = (const float*)d_in[4];
    const void*  frozen = (const void*)d_in[5];
    float* out = (float*)d_out;

    cudaFuncSetAttribute(gemm1_mma, cudaFuncAttributeMaxDynamicSharedMemorySize, SMEM_TOTAL);
    cudaFuncSetAttribute(gemm2_mma, cudaFuncAttributeMaxDynamicSharedMemorySize, SMEM_TOTAL);

    convert_x<<<(M_ROWS * D_DIM / 4 + 255) / 256, 256>>>(x);
    convert_p<<<(N_POS * D_DIM / 4 + 255) / 256, 256>>>(pos);
    transpose_v<<<dim3(D_DIM / 32, N_POS / 32), dim3(32, 8)>>>(values);
    row_norm_x_kernel<<<M_ROWS, 128>>>(x);
    pos_stats_kernel<<<N_POS, 128>>>(pos, temp, fscale, frozen);

    gemm1_mma<<<dim3(N_POS / 256, M_ROWS / 128), 256, SMEM_TOTAL>>>();
    reduce_parts<<<(M_ROWS + 255) / 256, 256>>>();
    gemm2_mma<<<dim3(D_DIM / 256, M_ROWS / 128), 256, SMEM_TOTAL>>>(out);
}

// round 17
// speedup vs baseline: 1.2739x; 1.2739x over previous
#include <cuda_runtime.h>
#include <cuda_bf16.h>
#include <cstdint>
#include <math.h>

// Problem constants (fixed shapes from setup_inputs)
#define M_ROWS 16384   // B*T
#define N_POS  4096
#define D_DIM  512

// ---------------------------------------------------------------------------
// Scratch (__device__ globals; device-side access ONLY — host-passing a
// __device__ symbol as a kernel arg passes the inert host shadow (r5-r9 bug).
// Separate hi/lo arrays + LDS.32 fragment loads (r14 layout — proven fastest;
// the r15/16 interleaved LDS.64 layout half-warp-conflicts and is slower).
// ---------------------------------------------------------------------------
__device__ __align__(1024) __nv_bfloat16 g_Xhi[(size_t)M_ROWS * D_DIM];
__device__ __align__(1024) __nv_bfloat16 g_Xlo[(size_t)M_ROWS * D_DIM];
__device__ __align__(1024) __nv_bfloat16 g_Phi[(size_t)N_POS * D_DIM];
__device__ __align__(1024) __nv_bfloat16 g_Plo[(size_t)N_POS * D_DIM];
__device__ __align__(1024) __nv_bfloat16 g_Vthi[(size_t)D_DIM * N_POS];  // V^T
__device__ __align__(1024) __nv_bfloat16 g_Vtlo[(size_t)D_DIM * N_POS];
__device__ __align__(1024) __nv_bfloat16 g_Whi[(size_t)M_ROWS * N_POS];
__device__ __align__(1024) __nv_bfloat16 g_Wlo[(size_t)M_ROWS * N_POS];
__device__ __align__(1024) float g_xn[M_ROWS];
__device__ __align__(1024) float g_pn[N_POS];
__device__ __align__(1024) float g_invt[N_POS];
__device__ __align__(1024) float g_part[(size_t)M_ROWS * 16];
__device__ __align__(1024) float g_rowsum[M_ROWS];

// ---------------------------------------------------------------------------
// Base-target helpers (no 'a'-gated instructions: harness targets sm_103)
// ---------------------------------------------------------------------------
__device__ __forceinline__ uint32_t smem_u32(const void* p) {
    uint32_t a;
    asm("{ .reg .u64 t; cvta.to.shared.u64 t, %1; cvt.u32.u64 %0, t; }" : "=r"(a) : "l"(p));
    return a;
}
__device__ __forceinline__ void cp16(uint32_t dst, const void* src) {
    asm volatile("cp.async.cg.shared.global [%0], [%1], 16;" :: "r"(dst), "l"(src));
}
#define CP_COMMIT()  asm volatile("cp.async.commit_group;" ::: "memory")
#define CP_WAIT_0()  asm volatile("cp.async.wait_group 0;" ::: "memory")
#define CP_WAIT_1()  asm volatile("cp.async.wait_group 1;" ::: "memory")

__device__ __forceinline__ void mma16816(float* d, const uint32_t* a, uint32_t b0, uint32_t b1) {
    asm volatile("mma.sync.aligned.m16n8k16.row.col.f32.bf16.bf16.f32 "
        "{%0,%1,%2,%3}, {%4,%5,%6,%7}, {%8,%9}, {%0,%1,%2,%3};"
        : "+f"(d[0]), "+f"(d[1]), "+f"(d[2]), "+f"(d[3])
        : "r"(a[0]), "r"(a[1]), "r"(a[2]), "r"(a[3]), "r"(b0), "r"(b1));
}

// ---------------------------------------------------------------------------
// SMEM layout. CTA tile M=128, N=256, K-chunk=64 bf16. Warp tile 64x64 (2x4).
// Plain row-major, 144-byte padded rows: fragment LDS.32 bank = (4*lg+lt)
// mod 32 -> 32 distinct banks -> conflict-free. 144 % 16 == 0 for cp.async.
// ---------------------------------------------------------------------------
#define ROW_BYTES 144
#define A_TILE_BYTES (128 * ROW_BYTES)    // 18432
#define B_TILE_BYTES (256 * ROW_BYTES)    // 36864
#define OFF_PN   0                        // 256 floats
#define OFF_IT   1024                     // 256 floats
#define OFF_RED  2048                     // 128*4 floats
#define OFF_BUF  4096
#define A_BUF(b, l) (OFF_BUF + ((b) * 2 + (l)) * A_TILE_BYTES)
#define B_BUF(b, l) (OFF_BUF + 4 * A_TILE_BYTES + ((b) * 2 + (l)) * B_TILE_BYTES)
#define SMEM_TOTAL (OFF_BUF + 4 * A_TILE_BYTES + 4 * B_TILE_BYTES)   // 225280

// Load an nrows x 64-col bf16 tile into padded smem (256 threads)
template <int NROWS>
__device__ __forceinline__ void load_tile(uint32_t base, uint32_t dst_off,
                                          const __nv_bfloat16* __restrict__ src,
                                          int row0, int ld, int k0, int tid) {
    #pragma unroll
    for (int i = 0; i < NROWS / 32; i++) {   // NROWS*8 chunks / 256 threads
        int idx = tid + i * 256;
        int row = idx >> 3, cc = idx & 7;
        const void* g = src + (size_t)(row0 + row) * ld + k0 + cc * 8;
        cp16(base + dst_off + (uint32_t)(row * ROW_BYTES + cc * 16), g);
    }
}

__device__ __forceinline__ void load_stage(uint32_t base, int b,
        const __nv_bfloat16* Ahi, const __nv_bfloat16* Alo, int ldA, int arow0,
        const __nv_bfloat16* Bhi, const __nv_bfloat16* Blo, int ldB, int brow0,
        int k0, int tid) {
    load_tile<128>(base, A_BUF(b, 0), Ahi, arow0, ldA, k0, tid);
    load_tile<128>(base, A_BUF(b, 1), Alo, arow0, ldA, k0, tid);
    load_tile<256>(base, B_BUF(b, 0), Bhi, brow0, ldB, k0, tid);
    load_tile<256>(base, B_BUF(b, 1), Blo, brow0, ldB, k0, tid);
}

// Compute one K=64 chunk. Warp tile 64x64: mf=4 (16-row), nf=8 (8-col).
// Fragments per PTX mma.m16n8k16 tables (g=lane>>2, t=lane&3).
__device__ __forceinline__ void compute_chunk(const char* smem, int b, int wm, int wn,
                                              int lane, float acc[4][8][4]) {
    const char* Ah = smem + A_BUF(b, 0);
    const char* Al = smem + A_BUF(b, 1);
    const char* Bh = smem + B_BUF(b, 0);
    const char* Bl = smem + B_BUF(b, 1);
    const int lg = lane >> 2, lt = lane & 3;
    #pragma unroll
    for (int kk = 0; kk < 4; kk++) {
        const uint32_t kb0 = (uint32_t)(kk * 32 + lt * 4);   // k = kk*16 + 2t
        uint32_t bh0[8], bh1[8], bl0[8], bl1[8];
        #pragma unroll
        for (int nf = 0; nf < 8; nf++) {
            uint32_t ro = (uint32_t)((wn * 64 + nf * 8 + lg) * ROW_BYTES);
            bh0[nf] = *(const uint32_t*)(Bh + ro + kb0);
            bh1[nf] = *(const uint32_t*)(Bh + ro + kb0 + 16);
            bl0[nf] = *(const uint32_t*)(Bl + ro + kb0);
            bl1[nf] = *(const uint32_t*)(Bl + ro + kb0 + 16);
        }
        #pragma unroll
        for (int mf = 0; mf < 4; mf++) {
            uint32_t r0 = (uint32_t)((wm * 64 + mf * 16 + lg) * ROW_BYTES);
            uint32_t r1 = r0 + 8 * ROW_BYTES;
            uint32_t ah[4], al[4];
            ah[0] = *(const uint32_t*)(Ah + r0 + kb0);
            ah[1] = *(const uint32_t*)(Ah + r1 + kb0);
            ah[2] = *(const uint32_t*)(Ah + r0 + kb0 + 16);
            ah[3] = *(const uint32_t*)(Ah + r1 + kb0 + 16);
            al[0] = *(const uint32_t*)(Al + r0 + kb0);
            al[1] = *(const uint32_t*)(Al + r1 + kb0);
            al[2] = *(const uint32_t*)(Al + r0 + kb0 + 16);
            al[3] = *(const uint32_t*)(Al + r1 + kb0 + 16);
            #pragma unroll
            for (int nf = 0; nf < 8; nf++) {
                mma16816(acc[mf][nf], ah, bh0[nf], bh1[nf]);  // hi*hi
                mma16816(acc[mf][nf], ah, bl0[nf], bl1[nf]);  // hi*lo
                mma16816(acc[mf][nf], al, bh0[nf], bh1[nf]);  // lo*hi
            }
        }
    }
}

// Double-buffered cp.async mainloop (proven r13/14 ordering)
__device__ __forceinline__ void gemm_main(const char* smem, uint32_t base, int tid,
        int wm, int wn, int lane,
        const __nv_bfloat16* Ahi, const __nv_bfloat16* Alo, int ldA, int arow0,
        const __nv_bfloat16* Bhi, const __nv_bfloat16* Blo, int ldB, int brow0,
        int C, float acc[4][8][4]) {
    load_stage(base, 0, Ahi, Alo, ldA, arow0, Bhi, Blo, ldB, brow0, 0, tid);
    CP_COMMIT();
    for (int c = 0; c < C; c++) {
        int b = c & 1;
        if (c + 1 < C) {
            load_stage(base, b ^ 1, Ahi, Alo, ldA, arow0, Bhi, Blo, ldB, brow0,
                       (c + 1) * 64, tid);
            CP_COMMIT();
            CP_WAIT_1();
        } else {
            CP_WAIT_0();
        }
        __syncthreads();
        compute_chunk(smem, b, wm, wn, lane, acc);
        __syncthreads();
    }
}

// ---------------------------------------------------------------------------
// GEMM1: S = X @ P^T (TN), epilogue w = exp(-dist*invt) -> W hi/lo + partials
// ---------------------------------------------------------------------------
__global__ __launch_bounds__(256) void gemm1_mma() {
    extern __shared__ char smem[];
    uint32_t base = smem_u32(smem);
    int tid = threadIdx.x, wid = tid >> 5, lane = tid & 31;
    int wm = wid >> 2, wn = wid & 3;
    int bm = blockIdx.y * 128, bn = blockIdx.x * 256;

    float* sm_pn = (float*)(smem + OFF_PN);
    float* sm_it = (float*)(smem + OFF_IT);
    sm_pn[tid] = g_pn[bn + tid];
    sm_it[tid] = g_invt[bn + tid];

    float acc[4][8][4];
    #pragma unroll
    for (int i = 0; i < 4; i++)
        #pragma unroll
        for (int j = 0; j < 8; j++)
            #pragma unroll
            for (int k = 0; k < 4; k++) acc[i][j][k] = 0.0f;

    gemm_main(smem, base, tid, wm, wn, lane, g_Xhi, g_Xlo, D_DIM, bm,
              g_Phi, g_Plo, D_DIM, bn, D_DIM / 64, acc);

    // Epilogue
    float* redrows = (float*)(smem + OFF_RED);
    float rps[4][2];
    #pragma unroll
    for (int mf = 0; mf < 4; mf++) { rps[mf][0] = 0.0f; rps[mf][1] = 0.0f; }

    #pragma unroll
    for (int mf = 0; mf < 4; mf++) {
        int r0l = wm * 64 + mf * 16 + (lane >> 2);
        float xn0 = g_xn[bm + r0l], xn1 = g_xn[bm + r0l + 8];
        #pragma unroll
        for (int nf = 0; nf < 8; nf++) {
            int c0 = wn * 64 + nf * 8 + (lane & 3) * 2;
            float pn0 = sm_pn[c0], pn1 = sm_pn[c0 + 1];
            float it0 = sm_it[c0], it1 = sm_it[c0 + 1];
            #pragma unroll
            for (int half = 0; half < 2; half++) {
                float xn = half ? xn1 : xn0;
                float s0 = acc[mf][nf][half * 2 + 0];
                float s1 = acc[mf][nf][half * 2 + 1];
                float d20 = fmaxf(xn + pn0 - 2.0f * s0, 0.0f);
                float d21 = fmaxf(xn + pn1 - 2.0f * s1, 0.0f);
                float w0 = __expf(-sqrtf(d20) * it0);
                float w1 = __expf(-sqrtf(d21) * it1);
                rps[mf][half] += w0 + w1;
                __nv_bfloat162 hp, lp;
                hp.x = __float2bfloat16(w0); hp.y = __float2bfloat16(w1);
                lp.x = __float2bfloat16(w0 - __bfloat162float(hp.x));
                lp.y = __float2bfloat16(w1 - __bfloat162float(hp.y));
                size_t gb = (size_t)(bm + r0l + half * 8) * N_POS + bn + c0;
                *(__nv_bfloat162*)(g_Whi + gb) = hp;
                *(__nv_bfloat162*)(g_Wlo + gb) = lp;
            }
        }
    }
    // Deterministic rowsum partials (4 lanes/row -> 4 warp-cols -> 1 value)
    #pragma unroll
    for (int mf = 0; mf < 4; mf++)
        #pragma unroll
        for (int half = 0; half < 2; half++) {
            float v = rps[mf][half];
            v += __shfl_xor_sync(0xffffffffu, v, 1);
            v += __shfl_xor_sync(0xffffffffu, v, 2);
            if ((lane & 3) == 0)
                redrows[(wm * 64 + mf * 16 + (lane >> 2) + half * 8) * 4 + wn] = v;
        }
    __syncthreads();
    if (tid < 128) {
        float s = redrows[tid * 4 + 0] + redrows[tid * 4 + 1]
                + redrows[tid * 4 + 2] + redrows[tid * 4 + 3];
        g_part[(size_t)(bm + tid) * 16 + blockIdx.x] = s;
    }
}

// ---------------------------------------------------------------------------
// GEMM2: out = (W @ V) / (rowsum + 1e-8)   (TN with B = V^T)
// ---------------------------------------------------------------------------
__global__ __launch_bounds__(256) void gemm2_mma(float* __restrict__ out) {
    extern __shared__ char smem[];
    uint32_t base = smem_u32(smem);
    int tid = threadIdx.x, wid = tid >> 5, lane = tid & 31;
    int wm = wid >> 2, wn = wid & 3;
    int bm = blockIdx.y * 128, dn = blockIdx.x * 256;

    float acc[4][8][4];
    #pragma unroll
    for (int i = 0; i < 4; i++)
        #pragma unroll
        for (int j = 0; j < 8; j++)
            #pragma unroll
            for (int k = 0; k < 4; k++) acc[i][j][k] = 0.0f;

    gemm_main(smem, base, tid, wm, wn, lane, g_Whi, g_Wlo, N_POS, bm,
              g_Vthi, g_Vtlo, N_POS, dn, N_POS / 64, acc);

    #pragma unroll
    for (int mf = 0; mf < 4; mf++) {
        int r0g = bm + wm * 64 + mf * 16 + (lane >> 2);
        float inv0 = 1.0f / (g_rowsum[r0g] + 1e-8f);
        float inv1 = 1.0f / (g_rowsum[r0g + 8] + 1e-8f);
        #pragma unroll
        for (int nf = 0; nf < 8; nf++) {
            int c0 = dn + wn * 64 + nf * 8 + (lane & 3) * 2;
            float2 v0 = make_float2(acc[mf][nf][0] * inv0, acc[mf][nf][1] * inv0);
            float2 v1 = make_float2(acc[mf][nf][2] * inv1, acc[mf][nf][3] * inv1);
            *(float2*)(out + (size_t)r0g * D_DIM + c0) = v0;
            *(float2*)(out + (size_t)(r0g + 8) * D_DIM + c0) = v1;
        }
    }
}

// ---------------------------------------------------------------------------
// Prep kernels (fused: convert + row norms/stats in one pass).
// Destinations are __device__ symbols, device-side access only.
// One block per 32 rows; each warp handles 4 rows (128-elem strips of 4).
// ---------------------------------------------------------------------------
__global__ __launch_bounds__(128) void convert_x_norm(const float* __restrict__ src) {
    // block covers rows [blockIdx.x*32, +32); thread t handles row r = t/4,
    // quarter q = t%4 (128 elements each = 32 float4)
    int r = blockIdx.x * 32 + (threadIdx.x >> 2);
    int q = threadIdx.x & 3;
    const float4* s4 = (const float4*)(src + (size_t)r * D_DIM + q * 128);
    size_t o = (size_t)r * D_DIM + q * 128;
    float acc = 0.0f;
    #pragma unroll 8
    for (int i = 0; i < 32; i++) {
        float4 v = s4[i];
        acc += v.x * v.x + v.y * v.y + v.z * v.z + v.w * v.w;
        __nv_bfloat16 h0 = __float2bfloat16(v.x), h1 = __float2bfloat16(v.y);
        __nv_bfloat16 h2 = __float2bfloat16(v.z), h3 = __float2bfloat16(v.w);
        __nv_bfloat16 hh[4] = {h0, h1, h2, h3};
        __nv_bfloat16 ll[4] = {
            __float2bfloat16(v.x - __bfloat162float(h0)),
            __float2bfloat16(v.y - __bfloat162float(h1)),
            __float2bfloat16(v.z - __bfloat162float(h2)),
            __float2bfloat16(v.w - __bfloat162float(h3))};
        *(uint2*)(g_Xhi + o + i * 4) = *(uint2*)hh;
        *(uint2*)(g_Xlo + o + i * 4) = *(uint2*)ll;
    }
    // reduce 4 threads of the same row (lanes q=0..3 adjacent)
    acc += __shfl_xor_sync(0xffffffffu, acc, 1);
    acc += __shfl_xor_sync(0xffffffffu, acc, 2);
    if (q == 0) g_xn[r] = acc;
}

__device__ __forceinline__ bool read_bool_elem(const void* p, int n) {
    unsigned int w0 = *(const unsigned int*)p;
    if (w0 == 0x3F800000u) return ((const float*)p)[n] != 0.0f;
    else if ((w0 & 0xFFu) != 0u && w0 != 1u) return ((const unsigned char*)p)[n] != 0;
    else return ((const int*)p)[n] != 0;
}

__global__ __launch_bounds__(128) void convert_p_stats(const float* __restrict__ src,
                                                       const float* __restrict__ temp,
                                                       const float* __restrict__ fscale,
                                                       const void* __restrict__ frozen) {
    int r = blockIdx.x * 32 + (threadIdx.x >> 2);
    int q = threadIdx.x & 3;
    const float4* s4 = (const float4*)(src + (size_t)r * D_DIM + q * 128);
    size_t o = (size_t)r * D_DIM + q * 128;
    float acc = 0.0f;
    #pragma unroll 8
    for (int i = 0; i < 32; i++) {
        float4 v = s4[i];
        acc += v.x * v.x + v.y * v.y + v.z * v.z + v.w * v.w;
        __nv_bfloat16 h0 = __float2bfloat16(v.x), h1 = __float2bfloat16(v.y);
        __nv_bfloat16 h2 = __float2bfloat16(v.z), h3 = __float2bfloat16(v.w);
        __nv_bfloat16 hh[4] = {h0, h1, h2, h3};
        __nv_bfloat16 ll[4] = {
            __float2bfloat16(v.x - __bfloat162float(h0)),
            __float2bfloat16(v.y - __bfloat162float(h1)),
            __float2bfloat16(v.z - __bfloat162float(h2)),
            __float2bfloat16(v.w - __bfloat162float(h3))};
        *(uint2*)(g_Phi + o + i * 4) = *(uint2*)hh;
        *(uint2*)(g_Plo + o + i * 4) = *(uint2*)ll;
    }
    acc += __shfl_xor_sync(0xffffffffu, acc, 1);
    acc += __shfl_xor_sync(0xffffffffu, acc, 2);
    if (q == 0) {
        g_pn[r] = acc;
        float es = read_bool_elem(frozen, r) ? fscale[r] : 0.05f;
        g_invt[r] = 1.0f / ((fabsf(temp[r]) + 0.1f) * es);
    }
}

__global__ void transpose_v(const float* __restrict__ V) {  // V[4096,512] -> Vt[512,4096] hi/lo
    __shared__ float t[32][33];
    int d0 = blockIdx.x * 32, n0 = blockIdx.y * 32;
    int tx = threadIdx.x, ty = threadIdx.y;
    #pragma unroll
    for (int i = 0; i < 4; i++)
        t[ty + i * 8][tx] = V[(size_t)(n0 + ty + i * 8) * D_DIM + d0 + tx];
    __syncthreads();
    #pragma unroll
    for (int i = 0; i < 4; i++) {
        int d = d0 + ty + i * 8;
        float v = t[tx][ty + i * 8];
        __nv_bfloat16 h = __float2bfloat16(v);
        g_Vthi[(size_t)d * N_POS + n0 + tx] = h;
        g_Vtlo[(size_t)d * N_POS + n0 + tx] = __float2bfloat16(v - __bfloat162float(h));
    }
}

__global__ void reduce_parts() {
    int row = blockIdx.x * blockDim.x + threadIdx.x;
    if (row >= M_ROWS) return;
    float s = 0.0f;
    #pragma unroll
    for (int i = 0; i < 16; i++) s += g_part[(size_t)row * 16 + i];
    g_rowsum[row] = s;
}

// ---------------------------------------------------------------------------
// Launch
// ---------------------------------------------------------------------------
extern "C" void kernel_launch(void* const* d_in, const int* in_sizes, int n_in,
                              void* d_out, int out_size) {
    const float* x      = (const float*)d_in[0];
    const float* pos    = (const float*)d_in[1];
    const float* values = (const float*)d_in[2];
    const float* temp   = (const float*)d_in[3];
    const float* fscale = (const float*)d_in[4];
    const void*  frozen = (const void*)d_in[5];
    float* out = (float*)d_out;

    cudaFuncSetAttribute(gemm1_mma, cudaFuncAttributeMaxDynamicSharedMemorySize, SMEM_TOTAL);
    cudaFuncSetAttribute(gemm2_mma, cudaFuncAttributeMaxDynamicSharedMemorySize, SMEM_TOTAL);

    convert_x_norm<<<M_ROWS / 32, 128>>>(x);
    convert_p_stats<<<N_POS / 32, 128>>>(pos, temp, fscale, frozen);
    transpose_v<<<dim3(D_DIM / 32, N_POS / 32), dim3(32, 8)>>>(values);

    gemm1_mma<<<dim3(N_POS / 256, M_ROWS / 128), 256, SMEM_TOTAL>>>();
    reduce_parts<<<(M_ROWS + 255) / 256, 256>>>();
    gemm2_mma<<<dim3(D_DIM / 256, M_ROWS / 128), 256, SMEM_TOTAL>>>(out);
}